// round 6
// baseline (speedup 1.0000x reference)
#include <cuda_runtime.h>
#include <cuda_bf16.h>

// 3x3 median blur, zero padding, 48 planes of 512x512 fp32.
// R6: R5 rolling-window structure (4-wide x TILE_H-tall per thread) plus
// dual-pipe compare-exchange: FMNMX lives only on the alu pipe (60% busy),
// the fma pipe is idle, so ~half the column-sort CEs are computed
// arithmetically (min=(s-|d|)/2, max=(s+|d|)/2 -> FADD/FMUL on fma pipe).
// 3 fma-ops replace 1 alu-op; offloading 9/18 CEs per 4 outputs balances
// the pipes (~11.6 us each) instead of serializing on alu (~14.7 us).

constexpr int W = 512;
constexpr int H = 512;
constexpr int TILE_H = 8;

__device__ __forceinline__ float med3f(float a, float b, float c) {
    return fmaxf(fminf(a, b), fminf(fmaxf(a, b), c));
}

// Compare-exchange on the alu pipe (FMNMX x2).
__device__ __forceinline__ void ce_alu(float& a, float& b) {
    float t = fminf(a, b);
    b = fmaxf(a, b);
    a = t;
}

// Compare-exchange on the fma pipe (FADD x4 + FMUL x2); |d| folds into FADD.
__device__ __forceinline__ void ce_fma(float& a, float& b) {
    const float s  = a + b;
    const float ad = fabsf(a - b);
    a = (s - ad) * 0.5f;
    b = (s + ad) * 0.5f;
}

// Load 6 columns [x0-1 .. x0+4] of row yy into c (zeros outside the plane).
__device__ __forceinline__ void load6(float c[6], const float* __restrict__ pb,
                                      int yy, int x0) {
    if (yy < 0 || yy >= H) {
        #pragma unroll
        for (int i = 0; i < 6; i++) c[i] = 0.0f;
        return;
    }
    const float* row = pb + (size_t)yy * W;
    const float4 v = *reinterpret_cast<const float4*>(row + x0);
    c[1] = v.x; c[2] = v.y; c[3] = v.z; c[4] = v.w;
    c[0] = (x0 > 0)     ? __ldg(row + x0 - 1) : 0.0f;
    c[5] = (x0 + 4 < W) ? __ldg(row + x0 + 4) : 0.0f;
}

// Sort columns (mixed-pipe CEs), merge 4 overlapping triples, store one row.
__device__ __forceinline__ void window_store(const float r0[6], const float r1[6],
                                             const float r2[6],
                                             float* __restrict__ q) {
    float lo[6], mi[6], hi[6];
    #pragma unroll
    for (int i = 0; i < 6; i++) {
        float a = r0[i], b = r1[i], c = r2[i];
        ce_fma(a, b);                        // offloaded: all 6 columns
        ce_alu(b, c);
        if (i & 1) ce_fma(a, b); else ce_alu(a, b);  // offloaded: 3 of 6
        lo[i] = a; mi[i] = b; hi[i] = c;
    }
    float res[4];
    #pragma unroll
    for (int j = 0; j < 4; j++) {
        const float mx = fmaxf(fmaxf(lo[j], lo[j + 1]), lo[j + 2]);
        const float mn = fminf(fminf(hi[j], hi[j + 1]), hi[j + 2]);
        const float md = med3f(mi[j], mi[j + 1], mi[j + 2]);
        res[j] = med3f(mx, md, mn);
    }
    float4 o;
    o.x = res[0]; o.y = res[1]; o.z = res[2]; o.w = res[3];
    *reinterpret_cast<float4*>(q) = o;
}

__global__ void __launch_bounds__(512) median3x3_kernel(
    const float* __restrict__ in, float* __restrict__ out)
{
    const int plane = blockIdx.y;                                   // 0..47
    const int x0    = threadIdx.x * 4;                              // 0..508
    const int y0    = (blockIdx.x * 4 + threadIdx.y) * TILE_H;      // top row

    const float* pb = in  + (size_t)plane * (H * W);
    float*       qb = out + (size_t)plane * (H * W) + (size_t)y0 * W + x0;

    // Rolling 3-row window in registers.
    float rows[3][6];
    load6(rows[0], pb, y0 - 1, x0);
    load6(rows[1], pb, y0,     x0);
    load6(rows[2], pb, y0 + 1, x0);

    #pragma unroll
    for (int t = 0; t < TILE_H; t++) {
        window_store(rows[t % 3], rows[(t + 1) % 3], rows[(t + 2) % 3],
                     qb + (size_t)t * W);
        if (t < TILE_H - 1)
            load6(rows[t % 3], pb, y0 + t + 2, x0);  // overwrite oldest row
    }
}

extern "C" void kernel_launch(void* const* d_in, const int* in_sizes, int n_in,
                              void* d_out, int out_size)
{
    const float* in  = (const float*)d_in[0];
    float*       out = (float*)d_out;

    // Block: 128 x-groups (4 px) x 4 tile-rows; each thread does TILE_H rows.
    dim3 block(128, 4, 1);
    dim3 grid(512 / (4 * TILE_H), 48, 1);
    median3x3_kernel<<<grid, block>>>(in, out);
}

// round 7
// speedup vs baseline: 1.0331x; 1.0331x over previous
#include <cuda_runtime.h>
#include <cuda_bf16.h>

// 3x3 median blur, zero padding, 48 planes of 512x512 fp32.
// R7: R5's proven layout (4-wide x 4-tall rolling window, LDG.128 + 2 scalar
// halos, TILE_H=4, grid 1536) with exact op-count reduction 21 -> 17.5/output:
//  - vertical: windows t,t+1 share the sorted middle row-pair; each window is
//    an insert-into-sorted-pair (4 ops/col) instead of a full sort3 (6 ops)
//  - horizontal: max3/min3 chains share interior pairwise extremes, and the
//    mid-median is a 2-op clamp into a sorted pair shared by 2 outputs.

constexpr int W = 512;
constexpr int H = 512;

__device__ __forceinline__ float med3f(float a, float b, float c) {
    return fmaxf(fminf(a, b), fminf(fmaxf(a, b), c));
}

// Load 6 columns [x0-1 .. x0+4] of row yy into c (zeros outside the plane).
__device__ __forceinline__ void load6(float c[6], const float* __restrict__ pb,
                                      int yy, int x0) {
    if (yy < 0 || yy >= H) {
        #pragma unroll
        for (int i = 0; i < 6; i++) c[i] = 0.0f;
        return;
    }
    const float* row = pb + (size_t)yy * W;
    const float4 v = *reinterpret_cast<const float4*>(row + x0);
    c[1] = v.x; c[2] = v.y; c[3] = v.z; c[4] = v.w;
    c[0] = (x0 > 0)     ? __ldg(row + x0 - 1) : 0.0f;
    c[5] = (x0 + 4 < W) ? __ldg(row + x0 + 4) : 0.0f;
}

// One output row: insert row r into the sorted pair (a<=b), then merge the
// 4 overlapping column-triples with shared pairwise extremes.
__device__ __forceinline__ void window_ins_store(
    const float a[6], const float b[6], const float r[6],
    float* __restrict__ q)
{
    float lo[6], mi[6], hi[6];
    #pragma unroll
    for (int i = 0; i < 6; i++) {
        const float mbr = fminf(b[i], r[i]);
        lo[i] = fminf(a[i], r[i]);
        mi[i] = fmaxf(a[i], mbr);
        hi[i] = fmaxf(b[i], r[i]);
    }

    // max-of-los with shared interior pairs
    const float pmx1 = fmaxf(lo[1], lo[2]);
    const float pmx3 = fmaxf(lo[3], lo[4]);
    const float mx0 = fmaxf(lo[0], pmx1);
    const float mx1 = fmaxf(pmx1, lo[3]);
    const float mx2 = fmaxf(lo[2], pmx3);
    const float mx3 = fmaxf(pmx3, lo[5]);

    // min-of-his with shared interior pairs
    const float pmn1 = fminf(hi[1], hi[2]);
    const float pmn3 = fminf(hi[3], hi[4]);
    const float mn0 = fminf(hi[0], pmn1);
    const float mn1 = fminf(pmn1, hi[3]);
    const float mn2 = fminf(hi[2], pmn3);
    const float mn3 = fminf(pmn3, hi[5]);

    // med-of-mids: clamp the third element into a shared sorted pair
    const float s12 = fminf(mi[1], mi[2]);
    const float t12 = fmaxf(mi[1], mi[2]);
    const float s34 = fminf(mi[3], mi[4]);
    const float t34 = fmaxf(mi[3], mi[4]);
    const float md0 = fmaxf(s12, fminf(t12, mi[0]));
    const float md1 = fmaxf(s12, fminf(t12, mi[3]));
    const float md2 = fmaxf(s34, fminf(t34, mi[2]));
    const float md3 = fmaxf(s34, fminf(t34, mi[5]));

    float4 o;
    o.x = med3f(mx0, md0, mn0);
    o.y = med3f(mx1, md1, mn1);
    o.z = med3f(mx2, md2, mn2);
    o.w = med3f(mx3, md3, mn3);
    *reinterpret_cast<float4*>(q) = o;
}

__global__ void __launch_bounds__(512) median3x3_kernel(
    const float* __restrict__ in, float* __restrict__ out)
{
    const int plane = blockIdx.y;                               // 0..47
    const int x0    = threadIdx.x * 4;                          // 0..508
    const int y0    = (blockIdx.x * 4 + threadIdx.y) * 4;       // top output row

    const float* pbase = in  + (size_t)plane * (H * W);
    float*       qb    = out + (size_t)plane * (H * W) + (size_t)y0 * W + x0;

    float rm1[6], r0[6], r1[6], r2[6], r3[6], r4[6];
    float pa[6], pb2[6];

    // Rows for windows 0 and 1 (batched for MLP).
    load6(rm1, pbase, y0 - 1, x0);
    load6(r0,  pbase, y0,     x0);
    load6(r1,  pbase, y0 + 1, x0);
    load6(r2,  pbase, y0 + 2, x0);

    // Shared sorted pair of rows (y0, y0+1).
    #pragma unroll
    for (int i = 0; i < 6; i++) {
        pa[i]  = fminf(r0[i], r1[i]);
        pb2[i] = fmaxf(r0[i], r1[i]);
    }
    window_ins_store(pa, pb2, rm1, qb);              // rows y0-1..y0+1
    window_ins_store(pa, pb2, r2,  qb + W);          // rows y0..y0+2

    // Rows for windows 2 and 3.
    load6(r3, pbase, y0 + 3, x0);
    load6(r4, pbase, y0 + 4, x0);

    // Shared sorted pair of rows (y0+2, y0+3).
    #pragma unroll
    for (int i = 0; i < 6; i++) {
        pa[i]  = fminf(r2[i], r3[i]);
        pb2[i] = fmaxf(r2[i], r3[i]);
    }
    window_ins_store(pa, pb2, r1, qb + 2 * W);       // rows y0+1..y0+3
    window_ins_store(pa, pb2, r4, qb + 3 * W);       // rows y0+2..y0+4
}

extern "C" void kernel_launch(void* const* d_in, const int* in_sizes, int n_in,
                              void* d_out, int out_size)
{
    const float* in  = (const float*)d_in[0];
    float*       out = (float*)d_out;

    // Block: 128 x-groups (4 px) x 4 tile-rows; each thread does 4 rows.
    dim3 block(128, 4, 1);
    dim3 grid(512 / 16, 48, 1);
    median3x3_kernel<<<grid, block>>>(in, out);
}

// round 8
// speedup vs baseline: 1.1048x; 1.0694x over previous
#include <cuda_runtime.h>
#include <cuda_bf16.h>

// 3x3 median blur, zero padding, 48 planes of 512x512 fp32.
// R8: identical math to R7 (17.5 exact min/max ops per output via shared
// sorted row-pairs + shared horizontal extremes), but 256-thread blocks:
// at 48 regs/thread, 512-thr blocks fit only 2/SM (50% occ ceiling, measured
// 42%); 256-thr blocks fit 5/SM (62.5% ceiling) and halve wave quantization.

constexpr int W = 512;
constexpr int H = 512;

__device__ __forceinline__ float med3f(float a, float b, float c) {
    return fmaxf(fminf(a, b), fminf(fmaxf(a, b), c));
}

// Load 6 columns [x0-1 .. x0+4] of row yy into c (zeros outside the plane).
__device__ __forceinline__ void load6(float c[6], const float* __restrict__ pb,
                                      int yy, int x0) {
    if (yy < 0 || yy >= H) {
        #pragma unroll
        for (int i = 0; i < 6; i++) c[i] = 0.0f;
        return;
    }
    const float* row = pb + (size_t)yy * W;
    const float4 v = *reinterpret_cast<const float4*>(row + x0);
    c[1] = v.x; c[2] = v.y; c[3] = v.z; c[4] = v.w;
    c[0] = (x0 > 0)     ? __ldg(row + x0 - 1) : 0.0f;
    c[5] = (x0 + 4 < W) ? __ldg(row + x0 + 4) : 0.0f;
}

// One output row: insert row r into the sorted pair (a<=b), then merge the
// 4 overlapping column-triples with shared pairwise extremes.
__device__ __forceinline__ void window_ins_store(
    const float a[6], const float b[6], const float r[6],
    float* __restrict__ q)
{
    float lo[6], mi[6], hi[6];
    #pragma unroll
    for (int i = 0; i < 6; i++) {
        const float mbr = fminf(b[i], r[i]);
        lo[i] = fminf(a[i], r[i]);
        mi[i] = fmaxf(a[i], mbr);
        hi[i] = fmaxf(b[i], r[i]);
    }

    // max-of-los with shared interior pairs
    const float pmx1 = fmaxf(lo[1], lo[2]);
    const float pmx3 = fmaxf(lo[3], lo[4]);
    const float mx0 = fmaxf(lo[0], pmx1);
    const float mx1 = fmaxf(pmx1, lo[3]);
    const float mx2 = fmaxf(lo[2], pmx3);
    const float mx3 = fmaxf(pmx3, lo[5]);

    // min-of-his with shared interior pairs
    const float pmn1 = fminf(hi[1], hi[2]);
    const float pmn3 = fminf(hi[3], hi[4]);
    const float mn0 = fminf(hi[0], pmn1);
    const float mn1 = fminf(pmn1, hi[3]);
    const float mn2 = fminf(hi[2], pmn3);
    const float mn3 = fminf(pmn3, hi[5]);

    // med-of-mids: clamp the third element into a shared sorted pair
    const float s12 = fminf(mi[1], mi[2]);
    const float t12 = fmaxf(mi[1], mi[2]);
    const float s34 = fminf(mi[3], mi[4]);
    const float t34 = fmaxf(mi[3], mi[4]);
    const float md0 = fmaxf(s12, fminf(t12, mi[0]));
    const float md1 = fmaxf(s12, fminf(t12, mi[3]));
    const float md2 = fmaxf(s34, fminf(t34, mi[2]));
    const float md3 = fmaxf(s34, fminf(t34, mi[5]));

    float4 o;
    o.x = med3f(mx0, md0, mn0);
    o.y = med3f(mx1, md1, mn1);
    o.z = med3f(mx2, md2, mn2);
    o.w = med3f(mx3, md3, mn3);
    *reinterpret_cast<float4*>(q) = o;
}

__global__ void __launch_bounds__(256) median3x3_kernel(
    const float* __restrict__ in, float* __restrict__ out)
{
    const int plane = blockIdx.y;                               // 0..47
    const int x0    = threadIdx.x * 4;                          // 0..508
    const int y0    = (blockIdx.x * 2 + threadIdx.y) * 4;       // top output row

    const float* pbase = in  + (size_t)plane * (H * W);
    float*       qb    = out + (size_t)plane * (H * W) + (size_t)y0 * W + x0;

    float rm1[6], r0[6], r1[6], r2[6], r3[6], r4[6];
    float pa[6], pb2[6];

    // Rows for windows 0 and 1 (batched for MLP).
    load6(rm1, pbase, y0 - 1, x0);
    load6(r0,  pbase, y0,     x0);
    load6(r1,  pbase, y0 + 1, x0);
    load6(r2,  pbase, y0 + 2, x0);

    // Shared sorted pair of rows (y0, y0+1).
    #pragma unroll
    for (int i = 0; i < 6; i++) {
        pa[i]  = fminf(r0[i], r1[i]);
        pb2[i] = fmaxf(r0[i], r1[i]);
    }
    window_ins_store(pa, pb2, rm1, qb);              // rows y0-1..y0+1
    window_ins_store(pa, pb2, r2,  qb + W);          // rows y0..y0+2

    // Rows for windows 2 and 3.
    load6(r3, pbase, y0 + 3, x0);
    load6(r4, pbase, y0 + 4, x0);

    // Shared sorted pair of rows (y0+2, y0+3).
    #pragma unroll
    for (int i = 0; i < 6; i++) {
        pa[i]  = fminf(r2[i], r3[i]);
        pb2[i] = fmaxf(r2[i], r3[i]);
    }
    window_ins_store(pa, pb2, r1, qb + 2 * W);       // rows y0+1..y0+3
    window_ins_store(pa, pb2, r4, qb + 3 * W);       // rows y0+2..y0+4
}

extern "C" void kernel_launch(void* const* d_in, const int* in_sizes, int n_in,
                              void* d_out, int out_size)
{
    const float* in  = (const float*)d_in[0];
    float*       out = (float*)d_out;

    // Block: 128 x-groups (4 px) x 2 tile-rows (256 thr); 4 rows per thread.
    dim3 block(128, 2, 1);
    dim3 grid(512 / 8, 48, 1);
    median3x3_kernel<<<grid, block>>>(in, out);
}